// round 1
// baseline (speedup 1.0000x reference)
#include <cuda_runtime.h>
#include <cstdint>
#include <math.h>

#define N_DET 10647
#define NW    167          // ceil(N_DET/64) mask words per row
#define SORT_M 16384
#define N_L0  8112         // 52*52*3
#define N_L01 10140        // + 26*26*3

// ---------------- scratch (static device globals; no runtime alloc) ----------------
__device__ float4 g_boxes[N_DET];                 // all_bbox (divided by 416), original order
__device__ int    g_cls[N_DET];
__device__ unsigned long long g_keys[SORT_M];     // (~fbits(score))<<32 | idx
__device__ float4 g_boxes_s[N_DET];               // sorted
__device__ float  g_areas_s[N_DET];
__device__ int    g_cls_s[N_DET];
__device__ int    g_orig[N_DET];
__device__ unsigned long long g_validmask[NW];
__device__ unsigned long long g_mask[(size_t)N_DET * NW];   // 14.2 MB suppression matrix

__device__ __forceinline__ float sigmoidf_(float x) { return 1.0f / (1.0f + expf(-x)); }

// ---------------- kernel 1: decode ----------------
__global__ void decode_kernel(const float* __restrict__ p0,
                              const float* __restrict__ p1,
                              const float* __restrict__ p2,
                              float* __restrict__ out)
{
    int gid = blockIdx.x * blockDim.x + threadIdx.x;
    if (gid < NW) g_validmask[gid] = 0ull;
    if (gid >= SORT_M) return;
    if (gid >= N_DET) { g_keys[gid] = ~0ull; return; }   // pad keys sort to the end

    // anchors (already scaled by 4/2/1 per level)
    const float AW[9] = {4.f, 8.f, 12.f, 3.f, 6.f, 8.f, 3.5f, 5.f, 8.f};
    const float AH[9] = {6.f, 12.f, 10.f, 7.f, 8.f, 6.f, 5.f, 4.5f, 8.f};

    const float* p; int W, HW, lvl, r; float s;
    if (gid < N_L0)       { p = p0; W = 52; HW = 2704; lvl = 0; r = gid;          s = 8.f;  }
    else if (gid < N_L01) { p = p1; W = 26; HW = 676;  lvl = 1; r = gid - N_L0;   s = 16.f; }
    else                  { p = p2; W = 13; HW = 169;  lvl = 2; r = gid - N_L01;  s = 32.f; }
    int hw = r / 3, a = r % 3;
    float gx = (float)(hw % W), gy = (float)(hw / W);
    float aw = AW[lvl * 3 + a], ah = AH[lvl * 3 + a];
    if (hw == HW - 1) { aw = 0.f; ah = 0.f; }            // reference zeroes last hw row

    const float* base = p + hw;                           // batch 0 only
    float obj = base[(size_t)a * HW];

    float l[20];
    #pragma unroll
    for (int c = 0; c < 20; c++) l[c] = base[(size_t)(3 + 20 * a + c) * HW];
    float m = l[0]; int am = 0;
    #pragma unroll
    for (int c = 1; c < 20; c++) { if (l[c] > m) { m = l[c]; am = c; } }
    float den = 0.f;
    #pragma unroll
    for (int c = 0; c < 20; c++) den += expf(l[c] - m);
    float score = sigmoidf_(obj) / den;                   // sigmoid(obj) * max softmax

    float tx = base[(size_t)(63 + 4 * a + 0) * HW];
    float ty = base[(size_t)(63 + 4 * a + 1) * HW];
    float tw = base[(size_t)(63 + 4 * a + 2) * HW];
    float th = base[(size_t)(63 + 4 * a + 3) * HW];
    float cx = sigmoidf_(tx) + gx;
    float cy = sigmoidf_(ty) + gy;
    float hx = expf(tw) * aw * 0.5f;
    float hy = expf(th) * ah * 0.5f;
    float x1 = ((cx - hx) * s) / 416.0f;
    float y1 = ((cy - hy) * s) / 416.0f;
    float x2 = ((cx + hx) * s) / 416.0f;
    float y2 = ((cy + hy) * s) / 416.0f;

    g_boxes[gid] = make_float4(x1, y1, x2, y2);
    g_cls[gid] = am;
    unsigned int fb = __float_as_uint(score);
    g_keys[gid] = (((unsigned long long)(~fb)) << 32) | (unsigned int)gid;

    // outputs: bboxes (clipped), scores, cls_inds
    out[4 * gid + 0] = fminf(fmaxf(x1 * 416.0f, 0.f), 415.f) / 416.0f;
    out[4 * gid + 1] = fminf(fmaxf(y1 * 416.0f, 0.f), 415.f) / 416.0f;
    out[4 * gid + 2] = fminf(fmaxf(x2 * 416.0f, 0.f), 415.f) / 416.0f;
    out[4 * gid + 3] = fminf(fmaxf(y2 * 416.0f, 0.f), 415.f) / 416.0f;
    out[4 * N_DET + gid] = score;
    out[5 * N_DET + gid] = (float)am;
}

// ---------------- kernel 2: single-block bitonic sort of 16384 u64 keys ----------------
__global__ void sort_kernel()
{
    extern __shared__ unsigned long long sk[];
    int tid = threadIdx.x;
    for (int i = tid; i < SORT_M; i += blockDim.x) sk[i] = g_keys[i];
    __syncthreads();
    for (int k = 2; k <= SORT_M; k <<= 1) {
        for (int j = k >> 1; j > 0; j >>= 1) {
            for (int t = tid; t < SORT_M / 2; t += blockDim.x) {
                int i = 2 * t - (t & (j - 1));
                int p = i | j;
                bool up = ((i & k) == 0);
                unsigned long long A = sk[i], B = sk[p];
                if ((A > B) == up) { sk[i] = B; sk[p] = A; }
            }
            __syncthreads();
        }
    }
    for (int i = tid; i < SORT_M; i += blockDim.x) g_keys[i] = sk[i];
}

// ---------------- kernel 3: reorder by sorted key + valid bitmask ----------------
__global__ void reorder_kernel()
{
    int si = blockIdx.x * blockDim.x + threadIdx.x;
    bool in = (si < N_DET);
    int valid = 0;
    if (in) {
        unsigned long long key = g_keys[si];
        int orig = (int)(unsigned int)key;
        float4 b = g_boxes[orig];
        g_boxes_s[si] = b;
        g_areas_s[si] = (b.z - b.x) * (b.w - b.y);
        g_cls_s[si]   = g_cls[orig];
        g_orig[si]    = orig;
        float score = __uint_as_float(~(unsigned int)(key >> 32));
        valid = (score >= 0.001f) ? 1 : 0;
    }
    unsigned ball = __ballot_sync(0xffffffffu, valid);
    if ((threadIdx.x & 31) == 0 && in) {
        atomicOr(&g_validmask[si >> 6], ((unsigned long long)ball) << (si & 63));
    }
}

// ---------------- kernel 4: suppression mask matrix (sorted index space) ----------------
__global__ void mask_kernel()
{
    int rt = blockIdx.y, ct = blockIdx.x;
    if (ct < rt) return;
    __shared__ float xs1[64], ys1[64], xs2[64], ys2[64], ar[64];
    __shared__ int   cl[64];
    int t = threadIdx.x;
    int j0 = ct * 64;
    int j = j0 + t;
    if (j < N_DET) {
        float4 b = g_boxes_s[j];
        xs1[t] = b.x; ys1[t] = b.y; xs2[t] = b.z; ys2[t] = b.w;
        ar[t] = g_areas_s[j];
        cl[t] = g_cls_s[j];
    } else {
        cl[t] = -1;
    }
    __syncthreads();
    int i = rt * 64 + t;
    if (i >= N_DET) return;
    float4 bi = g_boxes_s[i];
    float  ai = g_areas_s[i];
    int    ci = g_cls_s[i];
    unsigned long long w = 0;
    #pragma unroll 4
    for (int jj = 0; jj < 64; jj++) {
        int jg = j0 + jj;
        if (jg <= i) continue;              // idx > i (sorted order)
        if (cl[jj] != ci) continue;         // class must match (cheap pre-check)
        float xx1 = fmaxf(bi.x, xs1[jj]);
        float yy1 = fmaxf(bi.y, ys1[jj]);
        float xx2 = fminf(bi.z, xs2[jj]);
        float yy2 = fminf(bi.w, ys2[jj]);
        float inter = fmaxf(1e-28f, xx2 - xx1) * fmaxf(1e-28f, yy2 - yy1);
        float iou = inter / (ai + ar[jj] - inter);
        if (iou > 0.5f) w |= (1ull << jj);
    }
    g_mask[(size_t)i * NW + ct] = w;
}

// ---------------- kernel 5: sequential greedy reduce (single block) ----------------
__global__ void nms_kernel(float* __restrict__ out_keep)
{
    __shared__ unsigned long long rem[NW];
    __shared__ unsigned long long diag[64];
    __shared__ unsigned long long keptmask_sh;
    __shared__ int kept_rows[64];
    __shared__ int nkept_sh;
    int tid = threadIdx.x;
    for (int w = tid; w < NW; w += blockDim.x) rem[w] = 0ull;
    __syncthreads();

    for (int t = 0; t < NW; t++) {
        if (tid < 64) {
            int i = t * 64 + tid;
            diag[tid] = (i < N_DET) ? g_mask[(size_t)i * NW + t] : 0ull;
        }
        __syncthreads();
        if (tid == 0) {
            unsigned long long r  = rem[t];
            unsigned long long vm = g_validmask[t];
            unsigned long long kept = 0ull;
            int nk = 0;
            unsigned long long cand = vm & ~r;
            while (cand) {
                int b = __ffsll((long long)cand) - 1;
                kept |= (1ull << b);
                kept_rows[nk++] = t * 64 + b;
                r |= diag[b];                                  // within-tile suppression (bits > b only)
                unsigned long long hi = (b == 63) ? 0ull : (~0ull << (b + 1));
                cand = vm & ~r & hi;
            }
            rem[t] = r;
            keptmask_sh = kept;
            nkept_sh = nk;
        }
        __syncthreads();
        // scatter keep flags for this tile to original order
        if (tid < 64) {
            int i = t * 64 + tid;
            if (i < N_DET) out_keep[g_orig[i]] = (float)((keptmask_sh >> tid) & 1ull);
        }
        // OR kept rows' mask words into the future removed words (high MLP layout)
        int nk = nkept_sh;
        if (nk > 0 && t + 1 < NW) {
            int wslot = tid & 255;
            int grp   = tid >> 8;              // 4 row groups
            for (int w = t + 1 + wslot; w < NW; w += 256) {
                unsigned long long acc = 0ull;
                #pragma unroll 4
                for (int q = grp; q < nk; q += 4)
                    acc |= g_mask[(size_t)kept_rows[q] * NW + w];
                if (acc) atomicOr(&rem[w], acc);
            }
        }
        __syncthreads();
    }
}

// ---------------- launch ----------------
extern "C" void kernel_launch(void* const* d_in, const int* in_sizes, int n_in,
                              void* d_out, int out_size)
{
    const float* p0 = (const float*)d_in[0];   // (64, 75, 52, 52)
    const float* p1 = (const float*)d_in[1];   // (64, 75, 26, 26)
    const float* p2 = (const float*)d_in[2];   // (64, 75, 13, 13)
    float* out = (float*)d_out;                // [bboxes 4N | scores N | cls N | keep N]

    cudaFuncSetAttribute(sort_kernel, cudaFuncAttributeMaxDynamicSharedMemorySize,
                         SORT_M * (int)sizeof(unsigned long long));

    decode_kernel<<<SORT_M / 256, 256>>>(p0, p1, p2, out);
    sort_kernel<<<1, 1024, SORT_M * sizeof(unsigned long long)>>>();
    reorder_kernel<<<(N_DET + 255) / 256, 256>>>();
    dim3 mg(NW, NW);
    mask_kernel<<<mg, 64>>>();
    nms_kernel<<<1, 1024>>>(out + 6 * N_DET);
}

// round 3
// speedup vs baseline: 4.6009x; 4.6009x over previous
#include <cuda_runtime.h>
#include <cub/cub.cuh>
#include <cstdint>
#include <math.h>

#define N_DET   10647
#define NW      167            // ceil(N_DET/64)
#define N_L0    8112           // 52*52*3
#define N_L01   10140          // + 26*26*3
#define N_CLS   20
#define EDGE_CAP (1 << 22)     // 4M edges (16 MB)

// ---------------- static device scratch ----------------
__device__ float4 g_boxes[N_DET];                  // all_bbox (/416), original order
__device__ int    g_cls[N_DET];
__device__ unsigned int g_key32[N_DET];            // ~float_bits(score)
__device__ unsigned int g_val32[N_DET];            // original index
__device__ unsigned int g_key32_o[N_DET];
__device__ unsigned int g_val32_o[N_DET];          // g_orig in sorted order
__device__ float4 g_boxes_s[N_DET];                // sorted order
__device__ int    g_cls_s[N_DET];
__device__ unsigned long long g_validmask[NW];
__device__ int    g_clsCount[N_CLS];
__device__ int    g_classStart[N_CLS + 1];
__device__ unsigned int g_classlist[N_DET];        // (c<<20)|sorted_idx, stable per class
__device__ int    g_edgeCount;
__device__ unsigned int g_edges[EDGE_CAP];         // (i<<16)|j, sorted-space, i<j
__device__ __align__(256) unsigned char g_cub_tmp[1 << 22];   // 4 MB CUB temp

__device__ __forceinline__ float sigmoidf_(float x) { return 1.0f / (1.0f + expf(-x)); }

// ---------------- kernel 1: decode (coalesced) ----------------
__global__ void decode_kernel(const float* __restrict__ p0,
                              const float* __restrict__ p1,
                              const float* __restrict__ p2,
                              float* __restrict__ out)
{
    int gid = blockIdx.x * blockDim.x + threadIdx.x;
    // per-replay re-init of accumulators
    if (gid < NW)    g_validmask[gid] = 0ull;
    if (gid < N_CLS) g_clsCount[gid] = 0;
    if (gid == 0)    g_edgeCount = 0;
    if (gid >= N_DET) return;

    const float AW[9] = {4.f, 8.f, 12.f, 3.f, 6.f, 8.f, 3.5f, 5.f, 8.f};
    const float AH[9] = {6.f, 12.f, 10.f, 7.f, 8.f, 6.f, 5.f, 4.5f, 8.f};

    // thread mapping: within a level, t = a*HW + hw  (hw contiguous -> coalesced)
    const float* p; int W, HW, r, base_d, ai0; float s;
    if (gid < N_L0)       { p = p0; W = 52; HW = 2704; r = gid;          base_d = 0;     ai0 = 0; s = 8.f;  }
    else if (gid < N_L01) { p = p1; W = 26; HW = 676;  r = gid - N_L0;   base_d = N_L0;  ai0 = 3; s = 16.f; }
    else                  { p = p2; W = 13; HW = 169;  r = gid - N_L01;  base_d = N_L01; ai0 = 6; s = 32.f; }
    int a  = r / HW;
    int hw = r - a * HW;
    int d  = base_d + hw * 3 + a;              // detection index (reference order)

    float gx = (float)(hw % W), gy = (float)(hw / W);
    float aw = AW[ai0 + a], ah = AH[ai0 + a];
    if (hw == HW - 1) { aw = 0.f; ah = 0.f; }  // reference zeroes last hw row

    const float* base = p + hw;                 // batch 0
    float obj = base[(size_t)a * HW];

    float l[20];
    #pragma unroll
    for (int c = 0; c < 20; c++) l[c] = base[(size_t)(3 + 20 * a + c) * HW];
    float m = l[0]; int am = 0;
    #pragma unroll
    for (int c = 1; c < 20; c++) { if (l[c] > m) { m = l[c]; am = c; } }
    float den = 0.f;
    #pragma unroll
    for (int c = 0; c < 20; c++) den += expf(l[c] - m);
    float obj_s = sigmoidf_(obj);
    float sm    = 1.0f / den;                   // softmax at argmax == exp(0)/den
    float score = sm * obj_s;

    float tx = base[(size_t)(63 + 4 * a + 0) * HW];
    float ty = base[(size_t)(63 + 4 * a + 1) * HW];
    float tw = base[(size_t)(63 + 4 * a + 2) * HW];
    float th = base[(size_t)(63 + 4 * a + 3) * HW];
    float cx = sigmoidf_(tx) + gx;
    float cy = sigmoidf_(ty) + gy;
    float hx = expf(tw) * aw * 0.5f;
    float hy = expf(th) * ah * 0.5f;
    float x1 = ((cx - hx) * s) / 416.0f;
    float y1 = ((cy - hy) * s) / 416.0f;
    float x2 = ((cx + hx) * s) / 416.0f;
    float y2 = ((cy + hy) * s) / 416.0f;

    g_boxes[d] = make_float4(x1, y1, x2, y2);
    g_cls[d]   = am;
    g_key32[d] = ~__float_as_uint(score);
    g_val32[d] = (unsigned)d;

    float4 ob;
    ob.x = fminf(fmaxf(x1 * 416.0f, 0.f), 415.f) / 416.0f;
    ob.y = fminf(fmaxf(y1 * 416.0f, 0.f), 415.f) / 416.0f;
    ob.z = fminf(fmaxf(x2 * 416.0f, 0.f), 415.f) / 416.0f;
    ob.w = fminf(fmaxf(y2 * 416.0f, 0.f), 415.f) / 416.0f;
    reinterpret_cast<float4*>(out)[d] = ob;
    out[4 * N_DET + d] = score;
    out[5 * N_DET + d] = (float)am;
}

// ---------------- kernel 3: reorder + valid bitmask + class histogram ----------------
__global__ void reorder_kernel()
{
    int si = blockIdx.x * blockDim.x + threadIdx.x;
    bool in = (si < N_DET);
    int valid = 0;
    if (in) {
        unsigned key = g_key32_o[si];
        int orig = (int)g_val32_o[si];
        float4 b = g_boxes[orig];
        g_boxes_s[si] = b;
        int c = g_cls[orig];
        g_cls_s[si] = c;
        atomicAdd(&g_clsCount[c], 1);
        float score = __uint_as_float(~key);
        valid = (score >= 0.001f) ? 1 : 0;
    }
    unsigned ball = __ballot_sync(0xffffffffu, valid);
    if ((threadIdx.x & 31) == 0 && in)
        atomicOr(&g_validmask[si >> 6], ((unsigned long long)ball) << (si & 63));
}

// ---------------- kernel 4: tiny class-offset scan ----------------
__global__ void scan_kernel()
{
    if (threadIdx.x == 0) {
        int s = 0;
        for (int c = 0; c < N_CLS; c++) { g_classStart[c] = s; s += g_clsCount[c]; }
        g_classStart[N_CLS] = s;
    }
}

// ---------------- kernel 5: stable per-class compaction (20 blocks) ----------------
__global__ void bucket_kernel()
{
    int c = blockIdx.x;
    __shared__ int wtot[8];
    __shared__ int woff[8];
    int tid = threadIdx.x, lane = tid & 31, wid = tid >> 5;
    int base = g_classStart[c];
    int off = 0;
    for (int start = 0; start < N_DET; start += 256) {
        int i = start + tid;
        bool pred = (i < N_DET) && (g_cls_s[i] == c);
        unsigned mballot = __ballot_sync(0xffffffffu, pred);
        if (lane == 0) wtot[wid] = __popc(mballot);
        __syncthreads();
        if (tid == 0) {
            int s = 0;
            #pragma unroll
            for (int w = 0; w < 8; w++) { woff[w] = s; s += wtot[w]; }
        }
        __syncthreads();
        if (pred) {
            int rank = __popc(mballot & ((1u << lane) - 1u));
            g_classlist[base + off + woff[wid] + rank] = ((unsigned)c << 20) | (unsigned)i;
        }
        off += woff[7] + wtot[7];
        __syncthreads();
    }
}

// ---------------- kernel 6: sparse edge build (per-class pairwise) ----------------
__global__ void edge_kernel()
{
    int t = blockIdx.x * blockDim.x + threadIdx.x;
    if (t >= N_DET) return;
    unsigned ent = g_classlist[t];
    int c  = (int)(ent >> 20);
    int si = (int)(ent & 0xFFFFu);
    if (!((g_validmask[si >> 6] >> (si & 63)) & 1ull)) return;   // invalid rows never suppress
    int end = g_classStart[c + 1];
    float4 bi = g_boxes_s[si];
    float ai = (bi.z - bi.x) * (bi.w - bi.y);
    unsigned buf[64]; int cnt = 0;
    for (int p = t + 1; p < end; ++p) {
        int sj = (int)(g_classlist[p] & 0xFFFFu);
        float4 bj = g_boxes_s[sj];
        float xx1 = fmaxf(bi.x, bj.x);
        float yy1 = fmaxf(bi.y, bj.y);
        float xx2 = fminf(bi.z, bj.z);
        float yy2 = fminf(bi.w, bj.w);
        float inter = fmaxf(1e-28f, xx2 - xx1) * fmaxf(1e-28f, yy2 - yy1);
        float aj = (bj.z - bj.x) * (bj.w - bj.y);
        float iou = inter / (ai + aj - inter);
        if (iou > 0.5f) {
            if ((g_validmask[sj >> 6] >> (sj & 63)) & 1ull) {     // invalid targets don't matter
                buf[cnt++] = ((unsigned)si << 16) | (unsigned)sj;
                if (cnt == 64) {
                    int b = atomicAdd(&g_edgeCount, cnt);
                    for (int k = 0; k < cnt; k++)
                        if (b + k < EDGE_CAP) g_edges[b + k] = buf[k];
                    cnt = 0;
                }
            }
        }
    }
    if (cnt > 0) {
        int b = atomicAdd(&g_edgeCount, cnt);
        for (int k = 0; k < cnt; k++)
            if (b + k < EDGE_CAP) g_edges[b + k] = buf[k];
    }
}

// ---------------- kernel 7: greedy NMS via synchronous fixed point ----------------
// Edges go strictly low->high sorted index (a DAG), so the recursion
//   kept[i] = valid[i] & !removed[i];  removed[j] = OR_{(i,j)} kept[i]
// has a unique fixed point == greedy NMS. Jacobi-iterate (double buffer).
__global__ void nms_fp_kernel(float* __restrict__ out_keep)
{
    __shared__ unsigned long long svalid[NW], srem[NW], snew[NW];
    __shared__ int schanged;
    int tid = threadIdx.x;
    for (int w = tid; w < NW; w += 1024) { svalid[w] = g_validmask[w]; srem[w] = 0ull; }
    __syncthreads();
    int E = g_edgeCount; if (E > EDGE_CAP) E = EDGE_CAP;

    for (int it = 0; it < 2048; ++it) {
        for (int w = tid; w < NW; w += 1024) snew[w] = 0ull;
        if (tid == 0) schanged = 0;
        __syncthreads();
        for (int e = tid; e < E; e += 1024) {
            unsigned pk = g_edges[e];
            int i = (int)(pk >> 16), j = (int)(pk & 0xFFFFu);
            unsigned long long kb = svalid[i >> 6] & ~srem[i >> 6];
            if ((kb >> (i & 63)) & 1ull)
                atomicOr(&snew[j >> 6], 1ull << (j & 63));
        }
        __syncthreads();
        for (int w = tid; w < NW; w += 1024) {
            if (snew[w] != srem[w]) { srem[w] = snew[w]; schanged = 1; }
        }
        __syncthreads();
        int ch = schanged;
        __syncthreads();                 // protect schanged read vs next-iter write
        if (!ch) break;
    }
    __syncthreads();
    for (int i = tid; i < N_DET; i += 1024) {
        unsigned long long kb = svalid[i >> 6] & ~srem[i >> 6];
        out_keep[g_val32_o[i]] = (float)((kb >> (i & 63)) & 1ull);
    }
}

// ---------------- launch ----------------
extern "C" void kernel_launch(void* const* d_in, const int* in_sizes, int n_in,
                              void* d_out, int out_size)
{
    const float* p0 = (const float*)d_in[0];   // (64, 75, 52, 52)
    const float* p1 = (const float*)d_in[1];   // (64, 75, 26, 26)
    const float* p2 = (const float*)d_in[2];   // (64, 75, 13, 13)
    float* out = (float*)d_out;                // [bboxes 4N | scores N | cls N | keep N]

    void *dk, *dv, *dko, *dvo, *dtmp;
    cudaGetSymbolAddress(&dk,  g_key32);
    cudaGetSymbolAddress(&dv,  g_val32);
    cudaGetSymbolAddress(&dko, g_key32_o);
    cudaGetSymbolAddress(&dvo, g_val32_o);
    cudaGetSymbolAddress(&dtmp, g_cub_tmp);

    int nb = (N_DET + 255) / 256;
    decode_kernel<<<nb, 256>>>(p0, p1, p2, out);

    size_t tmp_bytes = sizeof(g_cub_tmp);
    cub::DeviceRadixSort::SortPairs(dtmp, tmp_bytes,
                                    (const unsigned int*)dk, (unsigned int*)dko,
                                    (const unsigned int*)dv, (unsigned int*)dvo,
                                    N_DET, 0, 32, (cudaStream_t)0);

    reorder_kernel<<<nb, 256>>>();
    scan_kernel<<<1, 32>>>();
    bucket_kernel<<<N_CLS, 256>>>();
    edge_kernel<<<nb, 256>>>();
    nms_fp_kernel<<<1, 1024>>>(out + 6 * N_DET);
}